// round 1
// baseline (speedup 1.0000x reference)
#include <cuda_runtime.h>
#include <math.h>

// ---------------------------------------------------------------------------
// DecoderLayer1MoEOnly: rmsnorm -> router top-6 (cap 192) -> grouped SwiGLU
// expert FFN + shared SwiGLU expert -> residual add.
// All fp32 SIMT for round 1 (tcgen05 tf32 port planned once baseline lands).
// ---------------------------------------------------------------------------

#define TOK 1024
#define HD  1280
#define NE  64
#define TKK 6
#define FD  896
#define FSD 1792
#define CP  192
#define REPS 1e-6f

// Scratch (static device globals: allocation-free per harness rules)
__device__ float g_xn[TOK * HD];          // rmsnorm output            5.2 MB
__device__ float g_w[TOK * TKK];          // top-k router probs
__device__ int   g_eidx[TOK * TKK];       // top-k expert ids
__device__ int   g_slot[TOK * TKK];       // slot in expert buffer, -1 dropped
__device__ int   g_cnt[NE];               // tokens per expert (clamped CP)
__device__ int   g_tok[NE * CP];          // slot -> token
__device__ float g_act[NE * CP * FD];     // silu(gate)*up            44 MB
__device__ float g_ye[NE * CP * HD];      // expert down output       63 MB
__device__ float g_sact[TOK * FSD];       // shared silu(g)*u          7.3 MB

// ---------------------------------------------------------------------------
// Kernel 1: rmsnorm + router logits + softmax + exact ordered top-6
// one block (128 threads) per token
// ---------------------------------------------------------------------------
__global__ void __launch_bounds__(128) k_rms_router(
    const float* __restrict__ x,
    const float* __restrict__ lnw,
    const float* __restrict__ rw)
{
    __shared__ float xs[HD];
    __shared__ float red[128];
    __shared__ float pr[NE];
    __shared__ float s_max, s_sum;

    const int t = blockIdx.x;
    const int tid = threadIdx.x;
    const float* xr = x + (size_t)t * HD;

    float ss = 0.f;
    for (int h = tid; h < HD; h += 128) {
        float v = xr[h];
        xs[h] = v;
        ss += v * v;
    }
    red[tid] = ss;
    __syncthreads();
#pragma unroll
    for (int s = 64; s > 0; s >>= 1) {
        if (tid < s) red[tid] += red[tid + s];
        __syncthreads();
    }
    const float rms = rsqrtf(red[0] / (float)HD + REPS);
    __syncthreads();

    for (int h = tid; h < HD; h += 128) {
        float v = xs[h] * rms * lnw[h];
        xs[h] = v;
        g_xn[(size_t)t * HD + h] = v;
    }
    __syncthreads();

    // router logits: thread e owns expert e (coalesced rw[h*NE+e])
    float lg = 0.f;
    if (tid < NE) {
        for (int h = 0; h < HD; ++h) lg += xs[h] * rw[h * NE + tid];
        red[tid] = lg;
    }
    __syncthreads();
    if (tid == 0) {
        float m = red[0];
        for (int e = 1; e < NE; ++e) m = fmaxf(m, red[e]);
        s_max = m;
    }
    __syncthreads();
    if (tid < NE) pr[tid] = expf(lg - s_max);
    __syncthreads();
    if (tid == 0) {
        float s = 0.f;
        for (int e = 0; e < NE; ++e) s += pr[e];
        s_sum = s;
    }
    __syncthreads();
    if (tid == 0) {
        const float inv = 1.f / s_sum;
        // descending top-6, ties -> lowest index (matches lax.top_k)
        for (int k = 0; k < TKK; ++k) {
            float best = -1.f;
            int bi = 0;
            for (int e = 0; e < NE; ++e) {
                float v = pr[e];
                if (v > best) { best = v; bi = e; }
            }
            g_eidx[t * TKK + k] = bi;
            g_w[t * TKK + k] = best * inv;
            pr[bi] = -2.f;
        }
    }
}

// ---------------------------------------------------------------------------
// Kernel 2: exact flat-order capacity assignment (reference cumsum order).
// one warp per expert scans all T*K entries with ballot prefix.
// ---------------------------------------------------------------------------
__global__ void k_route()
{
    const int e = blockIdx.x;
    const int lane = threadIdx.x;
    int base = 0;
    for (int i0 = 0; i0 < TOK * TKK; i0 += 32) {   // 6144 % 32 == 0
        const int i = i0 + lane;
        const bool m = (g_eidx[i] == e);
        const unsigned msk = __ballot_sync(0xffffffffu, m);
        if (m) {
            const int p = base + __popc(msk & ((1u << lane) - 1u));
            if (p < CP) {
                g_tok[e * CP + p] = i / TKK;
                g_slot[i] = p;
            } else {
                g_slot[i] = -1;
            }
        }
        base += __popc(msk);
    }
    if (lane == 0) g_cnt[e] = (base < CP) ? base : CP;
}

// ---------------------------------------------------------------------------
// Kernel 3: expert gate+up GEMM with row gather + fused silu.
// block tile 128(M) x 64(N) x 16(K), dual B (wg & wu), 256 threads, 8x4x2/thr.
// grid.x = e*2 + rowtile, grid.y = FD/64. Early-exit on empty row tiles.
// ---------------------------------------------------------------------------
__global__ void __launch_bounds__(256) k_gateup_expert(
    const float* __restrict__ wgp,
    const float* __restrict__ wup)
{
    const int bx = blockIdx.x;
    const int e = bx >> 1;
    const int row0 = (bx & 1) * 128;
    const int cnt = g_cnt[e];
    if (row0 >= cnt) return;
    const int n0 = blockIdx.y * 64;

    __shared__ float As[16][128];
    __shared__ float B1s[16][64];
    __shared__ float B2s[16][64];

    const int tid = threadIdx.x;
    const int* tokp = g_tok + e * CP;
    const float* B1 = wgp + (size_t)e * HD * FD;
    const float* B2 = wup + (size_t)e * HD * FD;

    const int arow = tid >> 2;
    const int ak = (tid & 3) << 2;
    const int r0 = row0 + arow;
    const int r1 = row0 + arow + 64;
    const float* a0 = (r0 < cnt) ? (g_xn + (size_t)tokp[r0] * HD) : 0;
    const float* a1 = (r1 < cnt) ? (g_xn + (size_t)tokp[r1] * HD) : 0;

    const int bk = tid >> 4;
    const int bn = (tid & 15) << 2;
    const int tr = (tid >> 4) << 3;
    const int tc = (tid & 15) << 2;

    float accg[8][4], accu[8][4];
#pragma unroll
    for (int i = 0; i < 8; i++)
#pragma unroll
        for (int j = 0; j < 4; j++) { accg[i][j] = 0.f; accu[i][j] = 0.f; }

    for (int k0 = 0; k0 < HD; k0 += 16) {
        const float4 z = make_float4(0.f, 0.f, 0.f, 0.f);
        float4 v0 = a0 ? *(const float4*)(a0 + k0 + ak) : z;
        float4 v1 = a1 ? *(const float4*)(a1 + k0 + ak) : z;
        float4 w1 = *(const float4*)(B1 + (size_t)(k0 + bk) * FD + n0 + bn);
        float4 w2 = *(const float4*)(B2 + (size_t)(k0 + bk) * FD + n0 + bn);
        __syncthreads();
        As[ak + 0][arow] = v0.x; As[ak + 1][arow] = v0.y;
        As[ak + 2][arow] = v0.z; As[ak + 3][arow] = v0.w;
        As[ak + 0][arow + 64] = v1.x; As[ak + 1][arow + 64] = v1.y;
        As[ak + 2][arow + 64] = v1.z; As[ak + 3][arow + 64] = v1.w;
        *(float4*)&B1s[bk][bn] = w1;
        *(float4*)&B2s[bk][bn] = w2;
        __syncthreads();
#pragma unroll
        for (int kk = 0; kk < 16; kk++) {
            const float4 av0 = *(const float4*)&As[kk][tr];
            const float4 av1 = *(const float4*)&As[kk][tr + 4];
            const float a[8] = {av0.x, av0.y, av0.z, av0.w, av1.x, av1.y, av1.z, av1.w};
            const float4 b1 = *(const float4*)&B1s[kk][tc];
            const float4 b2 = *(const float4*)&B2s[kk][tc];
            const float bb1[4] = {b1.x, b1.y, b1.z, b1.w};
            const float bb2[4] = {b2.x, b2.y, b2.z, b2.w};
#pragma unroll
            for (int i = 0; i < 8; i++)
#pragma unroll
                for (int j = 0; j < 4; j++) {
                    accg[i][j] += a[i] * bb1[j];
                    accu[i][j] += a[i] * bb2[j];
                }
        }
    }

    float* C = g_act + (size_t)e * CP * FD;
#pragma unroll
    for (int i = 0; i < 8; i++) {
        const int r = row0 + tr + i;
        if (r < CP) {
            float o[4];
#pragma unroll
            for (int j = 0; j < 4; j++) {
                const float g = accg[i][j];
                const float u = accu[i][j];
                o[j] = (g / (1.f + expf(-g))) * u;
            }
            *(float4*)&C[(size_t)r * FD + n0 + tc] = make_float4(o[0], o[1], o[2], o[3]);
        }
    }
}

// ---------------------------------------------------------------------------
// Kernel 4: shared-expert gate+up (dense rows), same tiling, fused silu.
// grid = (TOK/128, FSD/64)
// ---------------------------------------------------------------------------
__global__ void __launch_bounds__(256) k_gateup_shared(
    const float* __restrict__ B1g,
    const float* __restrict__ B2g)
{
    const int row0 = blockIdx.x * 128;
    const int n0 = blockIdx.y * 64;

    __shared__ float As[16][128];
    __shared__ float B1s[16][64];
    __shared__ float B2s[16][64];

    const int tid = threadIdx.x;
    const int arow = tid >> 2;
    const int ak = (tid & 3) << 2;
    const int bk = tid >> 4;
    const int bn = (tid & 15) << 2;
    const int tr = (tid >> 4) << 3;
    const int tc = (tid & 15) << 2;

    const float* a0 = g_xn + (size_t)(row0 + arow) * HD;
    const float* a1 = a0 + (size_t)64 * HD;

    float accg[8][4], accu[8][4];
#pragma unroll
    for (int i = 0; i < 8; i++)
#pragma unroll
        for (int j = 0; j < 4; j++) { accg[i][j] = 0.f; accu[i][j] = 0.f; }

    for (int k0 = 0; k0 < HD; k0 += 16) {
        float4 v0 = *(const float4*)(a0 + k0 + ak);
        float4 v1 = *(const float4*)(a1 + k0 + ak);
        float4 w1 = *(const float4*)(B1g + (size_t)(k0 + bk) * FSD + n0 + bn);
        float4 w2 = *(const float4*)(B2g + (size_t)(k0 + bk) * FSD + n0 + bn);
        __syncthreads();
        As[ak + 0][arow] = v0.x; As[ak + 1][arow] = v0.y;
        As[ak + 2][arow] = v0.z; As[ak + 3][arow] = v0.w;
        As[ak + 0][arow + 64] = v1.x; As[ak + 1][arow + 64] = v1.y;
        As[ak + 2][arow + 64] = v1.z; As[ak + 3][arow + 64] = v1.w;
        *(float4*)&B1s[bk][bn] = w1;
        *(float4*)&B2s[bk][bn] = w2;
        __syncthreads();
#pragma unroll
        for (int kk = 0; kk < 16; kk++) {
            const float4 av0 = *(const float4*)&As[kk][tr];
            const float4 av1 = *(const float4*)&As[kk][tr + 4];
            const float a[8] = {av0.x, av0.y, av0.z, av0.w, av1.x, av1.y, av1.z, av1.w};
            const float4 b1 = *(const float4*)&B1s[kk][tc];
            const float4 b2 = *(const float4*)&B2s[kk][tc];
            const float bb1[4] = {b1.x, b1.y, b1.z, b1.w};
            const float bb2[4] = {b2.x, b2.y, b2.z, b2.w};
#pragma unroll
            for (int i = 0; i < 8; i++)
#pragma unroll
                for (int j = 0; j < 4; j++) {
                    accg[i][j] += a[i] * bb1[j];
                    accu[i][j] += a[i] * bb2[j];
                }
        }
    }

#pragma unroll
    for (int i = 0; i < 8; i++) {
        const int r = row0 + tr + i;
        float o[4];
#pragma unroll
        for (int j = 0; j < 4; j++) {
            const float g = accg[i][j];
            const float u = accu[i][j];
            o[j] = (g / (1.f + expf(-g))) * u;
        }
        *(float4*)&g_sact[(size_t)r * FSD + n0 + tc] = make_float4(o[0], o[1], o[2], o[3]);
    }
}

// ---------------------------------------------------------------------------
// Kernel 5: expert down GEMM. tile 128x128x16, 256 threads, 8x8/thr.
// grid.x = e*2 + rowtile (early-exit), grid.y = HD/128
// ---------------------------------------------------------------------------
__global__ void __launch_bounds__(256) k_down_expert(const float* __restrict__ wdp)
{
    const int bx = blockIdx.x;
    const int e = bx >> 1;
    const int row0 = (bx & 1) * 128;
    const int cnt = g_cnt[e];
    if (row0 >= cnt) return;
    const int n0 = blockIdx.y * 128;

    __shared__ float As[16][128];
    __shared__ float Bs[16][128];

    const int tid = threadIdx.x;
    const float* A = g_act + (size_t)e * CP * FD;
    const float* B = wdp + (size_t)e * FD * HD;

    const int arow = tid >> 2;
    const int ak = (tid & 3) << 2;
    const int r0 = row0 + arow;
    const int r1 = r0 + 64;
    const int bk = tid >> 5;
    const int bn = (tid & 31) << 2;
    const int tr = (tid >> 4) << 3;
    const int tc = (tid & 15) << 3;

    float acc[8][8];
#pragma unroll
    for (int i = 0; i < 8; i++)
#pragma unroll
        for (int j = 0; j < 8; j++) acc[i][j] = 0.f;

    for (int k0 = 0; k0 < FD; k0 += 16) {
        const float4 z = make_float4(0.f, 0.f, 0.f, 0.f);
        float4 v0 = (r0 < CP) ? *(const float4*)(A + (size_t)r0 * FD + k0 + ak) : z;
        float4 v1 = (r1 < CP) ? *(const float4*)(A + (size_t)r1 * FD + k0 + ak) : z;
        float4 w0 = *(const float4*)(B + (size_t)(k0 + bk) * HD + n0 + bn);
        float4 w1 = *(const float4*)(B + (size_t)(k0 + bk + 8) * HD + n0 + bn);
        __syncthreads();
        As[ak + 0][arow] = v0.x; As[ak + 1][arow] = v0.y;
        As[ak + 2][arow] = v0.z; As[ak + 3][arow] = v0.w;
        As[ak + 0][arow + 64] = v1.x; As[ak + 1][arow + 64] = v1.y;
        As[ak + 2][arow + 64] = v1.z; As[ak + 3][arow + 64] = v1.w;
        *(float4*)&Bs[bk][bn] = w0;
        *(float4*)&Bs[bk + 8][bn] = w1;
        __syncthreads();
#pragma unroll
        for (int kk = 0; kk < 16; kk++) {
            const float4 av0 = *(const float4*)&As[kk][tr];
            const float4 av1 = *(const float4*)&As[kk][tr + 4];
            const float a[8] = {av0.x, av0.y, av0.z, av0.w, av1.x, av1.y, av1.z, av1.w};
            const float4 bv0 = *(const float4*)&Bs[kk][tc];
            const float4 bv1 = *(const float4*)&Bs[kk][tc + 4];
            const float b[8] = {bv0.x, bv0.y, bv0.z, bv0.w, bv1.x, bv1.y, bv1.z, bv1.w};
#pragma unroll
            for (int i = 0; i < 8; i++)
#pragma unroll
                for (int j = 0; j < 8; j++) acc[i][j] += a[i] * b[j];
        }
    }

    float* C = g_ye + (size_t)e * CP * HD;
#pragma unroll
    for (int i = 0; i < 8; i++) {
        const int r = row0 + tr + i;
        if (r < CP) {
            *(float4*)&C[(size_t)r * HD + n0 + tc] =
                make_float4(acc[i][0], acc[i][1], acc[i][2], acc[i][3]);
            *(float4*)&C[(size_t)r * HD + n0 + tc + 4] =
                make_float4(acc[i][4], acc[i][5], acc[i][6], acc[i][7]);
        }
    }
}

// ---------------------------------------------------------------------------
// Kernel 6: shared-expert down GEMM + residual. out = hidden + sact @ ws_d
// tile 128x128x16, grid (TOK/128, HD/128)
// ---------------------------------------------------------------------------
__global__ void __launch_bounds__(256) k_down_shared(
    const float* __restrict__ Bg,
    const float* __restrict__ hid,
    float* __restrict__ out)
{
    const int row0 = blockIdx.x * 128;
    const int n0 = blockIdx.y * 128;

    __shared__ float As[16][128];
    __shared__ float Bs[16][128];

    const int tid = threadIdx.x;
    const int arow = tid >> 2;
    const int ak = (tid & 3) << 2;
    const int bk = tid >> 5;
    const int bn = (tid & 31) << 2;
    const int tr = (tid >> 4) << 3;
    const int tc = (tid & 15) << 3;

    const float* a0 = g_sact + (size_t)(row0 + arow) * FSD;
    const float* a1 = a0 + (size_t)64 * FSD;

    float acc[8][8];
#pragma unroll
    for (int i = 0; i < 8; i++)
#pragma unroll
        for (int j = 0; j < 8; j++) acc[i][j] = 0.f;

    for (int k0 = 0; k0 < FSD; k0 += 16) {
        float4 v0 = *(const float4*)(a0 + k0 + ak);
        float4 v1 = *(const float4*)(a1 + k0 + ak);
        float4 w0 = *(const float4*)(Bg + (size_t)(k0 + bk) * HD + n0 + bn);
        float4 w1 = *(const float4*)(Bg + (size_t)(k0 + bk + 8) * HD + n0 + bn);
        __syncthreads();
        As[ak + 0][arow] = v0.x; As[ak + 1][arow] = v0.y;
        As[ak + 2][arow] = v0.z; As[ak + 3][arow] = v0.w;
        As[ak + 0][arow + 64] = v1.x; As[ak + 1][arow + 64] = v1.y;
        As[ak + 2][arow + 64] = v1.z; As[ak + 3][arow + 64] = v1.w;
        *(float4*)&Bs[bk][bn] = w0;
        *(float4*)&Bs[bk + 8][bn] = w1;
        __syncthreads();
#pragma unroll
        for (int kk = 0; kk < 16; kk++) {
            const float4 av0 = *(const float4*)&As[kk][tr];
            const float4 av1 = *(const float4*)&As[kk][tr + 4];
            const float a[8] = {av0.x, av0.y, av0.z, av0.w, av1.x, av1.y, av1.z, av1.w};
            const float4 bv0 = *(const float4*)&Bs[kk][tc];
            const float4 bv1 = *(const float4*)&Bs[kk][tc + 4];
            const float b[8] = {bv0.x, bv0.y, bv0.z, bv0.w, bv1.x, bv1.y, bv1.z, bv1.w};
#pragma unroll
            for (int i = 0; i < 8; i++)
#pragma unroll
                for (int j = 0; j < 8; j++) acc[i][j] += a[i] * b[j];
        }
    }

#pragma unroll
    for (int i = 0; i < 8; i++) {
        const int r = row0 + tr + i;
        const size_t base = (size_t)r * HD + n0 + tc;
        const float4 h0 = *(const float4*)&hid[base];
        const float4 h1 = *(const float4*)&hid[base + 4];
        *(float4*)&out[base] =
            make_float4(acc[i][0] + h0.x, acc[i][1] + h0.y, acc[i][2] + h0.z, acc[i][3] + h0.w);
        *(float4*)&out[base + 4] =
            make_float4(acc[i][4] + h1.x, acc[i][5] + h1.y, acc[i][6] + h1.z, acc[i][7] + h1.w);
    }
}

// ---------------------------------------------------------------------------
// Kernel 7: combine routed expert outputs. one block (128 thr) per token.
// out[t,h] += sum_k w[t,k] * ye[e(t,k), slot(t,k), h]
// ---------------------------------------------------------------------------
__global__ void __launch_bounds__(128) k_combine(float* __restrict__ out)
{
    const int t = blockIdx.x;
    const int tid = threadIdx.x;
    float acc[HD / 128];
#pragma unroll
    for (int j = 0; j < HD / 128; j++) acc[j] = 0.f;

    for (int k = 0; k < TKK; ++k) {
        const int s = g_slot[t * TKK + k];
        if (s < 0) continue;
        const int e = g_eidx[t * TKK + k];
        const float w = g_w[t * TKK + k];
        const float* yr = g_ye + ((size_t)e * CP + s) * HD;
#pragma unroll
        for (int j = 0; j < HD / 128; j++) acc[j] += w * yr[tid + j * 128];
    }
    float* orow = out + (size_t)t * HD;
#pragma unroll
    for (int j = 0; j < HD / 128; j++) orow[tid + j * 128] += acc[j];
}

// ---------------------------------------------------------------------------
extern "C" void kernel_launch(void* const* d_in, const int* in_sizes, int n_in,
                              void* d_out, int out_size)
{
    (void)in_sizes; (void)n_in; (void)out_size;
    const float* hidden = (const float*)d_in[0];
    // d_in[1] attention_mask, d_in[2] position_ids: unused by reference
    const float* lnw = (const float*)d_in[3];
    const float* rw  = (const float*)d_in[4];
    const float* wg  = (const float*)d_in[5];
    const float* wu  = (const float*)d_in[6];
    const float* wd  = (const float*)d_in[7];
    const float* wsg = (const float*)d_in[8];
    const float* wsu = (const float*)d_in[9];
    const float* wsd = (const float*)d_in[10];
    float* out = (float*)d_out;

    k_rms_router<<<TOK, 128>>>(hidden, lnw, rw);
    k_route<<<NE, 32>>>();
    k_gateup_expert<<<dim3(NE * 2, FD / 64), 256>>>(wg, wu);
    k_gateup_shared<<<dim3(TOK / 128, FSD / 64), 256>>>(wsg, wsu);
    k_down_expert<<<dim3(NE * 2, HD / 128), 256>>>(wd);
    k_down_shared<<<dim3(TOK / 128, HD / 128), 256>>>(wsd, hidden, out);
    k_combine<<<TOK, 128>>>(out);
}